// round 1
// baseline (speedup 1.0000x reference)
#include <cuda_runtime.h>

#define MUL   16
#define DD    4
#define S0    8
#define S1    8
#define SOUT  8
#define NP3   8
#define NP4   4
#define EPB   8          // edges per block
#define THREADS 128

// sout-sorted path list (built once per launch by prep_kernel; deterministic)
__device__ int  d_off[SOUT + 1];
__device__ int2 d_ent[NP3 + NP4];   // .x = s0 slot, .y = W slot (p3: 0..7, p4: 8..11)

__global__ void prep_kernel(const int* __restrict__ p3, const int* __restrict__ p4) {
    if (threadIdx.x == 0 && blockIdx.x == 0) {
        int n = 0;
        for (int so = 0; so < SOUT; ++so) {
            d_off[so] = n;
            for (int p = 0; p < NP3; ++p)
                if (p3[p * 3 + 2] == so) { d_ent[n] = make_int2(p3[p * 3 + 0], p); ++n; }
            for (int p = 0; p < NP4; ++p)
                if (p4[p * 4 + 3] == so) { d_ent[n] = make_int2(p4[p * 4 + 0], NP3 + p); ++n; }
        }
        d_off[SOUT] = n;
    }
}

__global__ __launch_bounds__(THREADS) void tp_kernel(
    const float* __restrict__ x0, const int* __restrict__ i0,
    const float* __restrict__ x1, const float* __restrict__ C3,
    const float* __restrict__ C4, const int* __restrict__ p3,
    const int* __restrict__ p4, float* __restrict__ out, int E)
{
    __shared__ float sX0[EPB][S0 * MUL * DD];   // 8 * 512 * 4B = 16 KB
    __shared__ float sX1[EPB][S1 * DD];         // 1 KB
    __shared__ float sW[EPB][(NP3 + NP4) * 16]; // 6 KB  (12 slots of [i][k])
    __shared__ float sC3[NP3 * DD * 20];        // padded: 32 slices x 20 floats
    __shared__ float sC4[NP4 * DD * 68];        // padded: 16 slices x 68 floats
    __shared__ int2  sEnt[NP3 + NP4];
    __shared__ int   sOff[SOUT + 1];
    __shared__ int   sP3s1[NP3];
    __shared__ int2  sP4s[NP4];

    const int tid = threadIdx.x;
    const int el  = tid >> 4;     // edge slot within block
    const int u   = tid & 15;     // mul index
    const int e   = blockIdx.x * EPB + el;
    const bool valid = (e < E);

    // ---- stage coefficients (bank-conflict-padded) + path metadata ----
    for (int idx = tid; idx < NP3 * DD * DD * DD; idx += THREADS) {
        int slice = idx >> 4;
        sC3[slice * 20 + (idx & 15)] = C3[idx];
    }
    for (int idx = tid; idx < NP4 * DD * DD * DD * DD; idx += THREADS) {
        int slice = idx >> 6;
        sC4[slice * 68 + (idx & 63)] = C4[idx];
    }
    if (tid < NP3 + NP4) sEnt[tid] = d_ent[tid];
    if (tid < SOUT + 1)  sOff[tid] = d_off[tid];
    if (tid < NP3)       sP3s1[tid] = p3[tid * 3 + 1];
    if (tid < NP4)       sP4s[tid]  = make_int2(p4[tid * 4 + 1], p4[tid * 4 + 2]);

    // ---- stage x0 (gathered row) and x1 ----
    if (valid) {
        const long long row = (long long)__ldg(&i0[e]) * (S0 * MUL * DD);
        #pragma unroll
        for (int c = 0; c < 8; ++c) {
            float4 v = *(const float4*)&x0[row + c * 64 + u * 4];
            *(float4*)&sX0[el][c * 64 + u * 4] = v;
        }
        if (u < 8) {
            float4 v = *(const float4*)&x1[(long long)e * (S1 * DD) + u * 4];
            *(float4*)&sX1[el][u * 4] = v;
        }
    }
    __syncthreads();

    // ---- W phase: factor out the x1 contractions once per edge ----
    if (valid) {
        // Step A: rank-4 jobs. job = u -> (p = u>>2, i = u&3). Uniform across lanes.
        {
            const int p = u >> 2;
            const int s1a = sP4s[p].x, s1b = sP4s[p].y;
            const float* Cs = &sC4[u * 68];       // slice (p,i), layout [j][k][m]
            float4 w = make_float4(0.f, 0.f, 0.f, 0.f);
            #pragma unroll
            for (int j = 0; j < 4; ++j) {
                const float bj = sX1[el][s1a * 4 + j];
                #pragma unroll
                for (int k = 0; k < 4; ++k) {
                    const float bc = bj * sX1[el][s1b * 4 + k];
                    float4 cv = *(const float4*)&Cs[(j * 4 + k) * 4];
                    w.x += bc * cv.x; w.y += bc * cv.y;
                    w.z += bc * cv.z; w.w += bc * cv.w;
                }
            }
            *(float4*)&sW[el][(NP3 << 4) + u * 4] = w;   // slot NP3+p, row i
        }
        // Step B: rank-3 jobs. jobs u and u+16 -> (p = job>>2, i = job&3).
        #pragma unroll
        for (int h = 0; h < 2; ++h) {
            const int job = u + 16 * h;
            const int p = job >> 2;
            const int s1 = sP3s1[p];
            const float* Cs = &sC3[job * 20];     // slice (p,i), layout [j][k]
            float4 w = make_float4(0.f, 0.f, 0.f, 0.f);
            #pragma unroll
            for (int j = 0; j < 4; ++j) {
                const float bj = sX1[el][s1 * 4 + j];
                float4 cv = *(const float4*)&Cs[j * 4];
                w.x += bj * cv.x; w.y += bj * cv.y;
                w.z += bj * cv.z; w.w += bj * cv.w;
            }
            *(float4*)&sW[el][job * 4] = w;       // slot p, row i
        }
    }
    __syncthreads();

    // ---- contraction: acc[k] = sum_paths sum_i a[s0][u][i] * W[slot][i][k] ----
    if (valid) {
        const long long obase = (long long)e * (SOUT * MUL * DD);
        #pragma unroll
        for (int so = 0; so < SOUT; ++so) {
            float4 acc = make_float4(0.f, 0.f, 0.f, 0.f);
            const int end = sOff[so + 1];
            for (int idx = sOff[so]; idx < end; ++idx) {
                const int2 en = sEnt[idx];
                float4 a  = *(const float4*)&sX0[el][en.x * 64 + u * 4];
                const float* Wp = &sW[el][en.y * 16];
                float4 w0 = *(const float4*)&Wp[0];
                float4 w1 = *(const float4*)&Wp[4];
                float4 w2 = *(const float4*)&Wp[8];
                float4 w3 = *(const float4*)&Wp[12];
                acc.x += a.x * w0.x + a.y * w1.x + a.z * w2.x + a.w * w3.x;
                acc.y += a.x * w0.y + a.y * w1.y + a.z * w2.y + a.w * w3.y;
                acc.z += a.x * w0.z + a.y * w1.z + a.z * w2.z + a.w * w3.z;
                acc.w += a.x * w0.w + a.y * w1.w + a.z * w2.w + a.w * w3.w;
            }
            *(float4*)&out[obase + so * 64 + u * 4] = acc;
        }
    }
}

extern "C" void kernel_launch(void* const* d_in, const int* in_sizes, int n_in,
                              void* d_out, int out_size) {
    const float* x0 = (const float*)d_in[0];
    const int*   i0 = (const int*)d_in[1];
    const float* x1 = (const float*)d_in[2];
    const float* C3 = (const float*)d_in[3];
    const float* C4 = (const float*)d_in[4];
    const int*   p3 = (const int*)d_in[5];
    const int*   p4 = (const int*)d_in[6];
    float* out = (float*)d_out;
    const int E = in_sizes[1];              // i0 has E elements

    prep_kernel<<<1, 32>>>(p3, p4);
    const int blocks = (E + EPB - 1) / EPB;
    tp_kernel<<<blocks, THREADS>>>(x0, i0, x1, C3, C4, p3, p4, out, E);
}

// round 2
// speedup vs baseline: 1.2209x; 1.2209x over previous
#include <cuda_runtime.h>

#define MUL   16
#define DD    4
#define S0    8
#define S1    8
#define SOUT  8
#define NP3   8
#define NP4   4
#define EPB   8          // edges per block
#define THREADS 128

// sout-sorted path list + per-path s1 metadata (built by prep_kernel)
__device__ int  d_off[SOUT + 1];
__device__ int2 d_ent[NP3 + NP4];   // .x = s0 slot, .y = W slot (p3: 0..7, p4: 8..11)
__device__ int  d_p3s1[NP3];
__device__ int2 d_p4s[NP4];

__global__ void prep_kernel(const int* __restrict__ p3, const int* __restrict__ p4) {
    if (threadIdx.x == 0 && blockIdx.x == 0) {
        int n = 0;
        for (int so = 0; so < SOUT; ++so) {
            d_off[so] = n;
            for (int p = 0; p < NP3; ++p)
                if (p3[p * 3 + 2] == so) { d_ent[n] = make_int2(p3[p * 3 + 0], p); ++n; }
            for (int p = 0; p < NP4; ++p)
                if (p4[p * 4 + 3] == so) { d_ent[n] = make_int2(p4[p * 4 + 0], NP3 + p); ++n; }
        }
        d_off[SOUT] = n;
        for (int p = 0; p < NP3; ++p) d_p3s1[p] = p3[p * 3 + 1];
        for (int p = 0; p < NP4; ++p) d_p4s[p]  = make_int2(p4[p * 4 + 1], p4[p * 4 + 2]);
    }
}

// uniform-index register select (en.x is uniform across the block -> uniform branch)
__device__ __forceinline__ float4 sel8(const float4 a[8], int s) {
    switch (s) {
        case 0: return a[0]; case 1: return a[1];
        case 2: return a[2]; case 3: return a[3];
        case 4: return a[4]; case 5: return a[5];
        case 6: return a[6]; default: return a[7];
    }
}

__global__ __launch_bounds__(THREADS, 6) void tp_kernel(
    const float* __restrict__ x0, const int* __restrict__ i0,
    const float* __restrict__ x1,
    const float* __restrict__ C3, const float* __restrict__ C4,
    float* __restrict__ out, int E)
{
    __shared__ float sX1[EPB][S1 * DD];         // 1 KB
    __shared__ float sW[EPB][(NP3 + NP4) * 16]; // 6 KB  (12 slots of [i][k])
    __shared__ float sC3[NP3 * DD * 20];        // padded slices
    __shared__ float sC4[NP4 * DD * 68];        // padded slices
    __shared__ int2  sEnt[NP3 + NP4];
    __shared__ int   sOff[SOUT + 1];
    __shared__ int   sP3s1[NP3];
    __shared__ int2  sP4s[NP4];

    const int tid = threadIdx.x;
    const int el  = tid >> 4;     // edge slot within block
    const int u   = tid & 15;     // mul index
    const int e   = blockIdx.x * EPB + el;
    const bool valid = (e < E);

    // ---- issue x0 gather into registers EARLY (8 independent LDG.128) ----
    float4 a[8];
    if (valid) {
        const long long row = (long long)__ldg(&i0[e]) * (S0 * MUL * DD);
        #pragma unroll
        for (int c = 0; c < 8; ++c)
            a[c] = __ldg((const float4*)&x0[row + c * 64 + u * 4]);
    }

    // ---- stage coefficients (bank-conflict-padded) + path metadata ----
    for (int idx = tid; idx < NP3 * DD * DD * DD; idx += THREADS) {
        int slice = idx >> 4;
        sC3[slice * 20 + (idx & 15)] = C3[idx];
    }
    for (int idx = tid; idx < NP4 * DD * DD * DD * DD; idx += THREADS) {
        int slice = idx >> 6;
        sC4[slice * 68 + (idx & 63)] = C4[idx];
    }
    if (tid < NP3 + NP4) sEnt[tid] = d_ent[tid];
    if (tid < SOUT + 1)  sOff[tid] = d_off[tid];
    if (tid < NP3)       sP3s1[tid] = d_p3s1[tid];
    if (tid < NP4)       sP4s[tid]  = d_p4s[tid];

    // ---- stage x1 ----
    if (valid && u < 8) {
        float4 v = __ldg((const float4*)&x1[(long long)e * (S1 * DD) + u * 4]);
        *(float4*)&sX1[el][u * 4] = v;
    }
    __syncthreads();

    // ---- W phase: factor out the x1 contractions once per edge ----
    if (valid) {
        // rank-4 job: (p = u>>2, i = u&3)
        {
            const int p = u >> 2;
            const int s1a = sP4s[p].x, s1b = sP4s[p].y;
            const float* Cs = &sC4[u * 68];
            float4 w = make_float4(0.f, 0.f, 0.f, 0.f);
            #pragma unroll
            for (int j = 0; j < 4; ++j) {
                const float bj = sX1[el][s1a * 4 + j];
                #pragma unroll
                for (int k = 0; k < 4; ++k) {
                    const float bc = bj * sX1[el][s1b * 4 + k];
                    float4 cv = *(const float4*)&Cs[(j * 4 + k) * 4];
                    w.x += bc * cv.x; w.y += bc * cv.y;
                    w.z += bc * cv.z; w.w += bc * cv.w;
                }
            }
            *(float4*)&sW[el][(NP3 << 4) + u * 4] = w;
        }
        // rank-3 jobs: u and u+16
        #pragma unroll
        for (int h = 0; h < 2; ++h) {
            const int job = u + 16 * h;
            const int p = job >> 2;
            const int s1 = sP3s1[p];
            const float* Cs = &sC3[job * 20];
            float4 w = make_float4(0.f, 0.f, 0.f, 0.f);
            #pragma unroll
            for (int j = 0; j < 4; ++j) {
                const float bj = sX1[el][s1 * 4 + j];
                float4 cv = *(const float4*)&Cs[j * 4];
                w.x += bj * cv.x; w.y += bj * cv.y;
                w.z += bj * cv.z; w.w += bj * cv.w;
            }
            *(float4*)&sW[el][job * 4] = w;
        }
    }
    __syncthreads();

    // ---- contraction: acc[k] = sum_paths sum_i a[s0][u][i] * W[slot][i][k] ----
    if (valid) {
        const long long obase = (long long)e * (SOUT * MUL * DD);
        #pragma unroll
        for (int so = 0; so < SOUT; ++so) {
            float4 acc = make_float4(0.f, 0.f, 0.f, 0.f);
            const int end = sOff[so + 1];
            for (int idx = sOff[so]; idx < end; ++idx) {
                const int2 en = sEnt[idx];
                const float4 av = sel8(a, en.x);
                const float4* Wp = (const float4*)&sW[el][en.y * 16];
                const float4 w0 = Wp[0], w1 = Wp[1], w2 = Wp[2], w3 = Wp[3];
                acc.x += av.x * w0.x + av.y * w1.x + av.z * w2.x + av.w * w3.x;
                acc.y += av.x * w0.y + av.y * w1.y + av.z * w2.y + av.w * w3.y;
                acc.z += av.x * w0.z + av.y * w1.z + av.z * w2.z + av.w * w3.z;
                acc.w += av.x * w0.w + av.y * w1.w + av.z * w2.w + av.w * w3.w;
            }
            // streaming store: don't pollute L2 (keep it for the x0 gather)
            __stwt((float4*)&out[obase + so * 64 + u * 4], acc);
        }
    }
}

extern "C" void kernel_launch(void* const* d_in, const int* in_sizes, int n_in,
                              void* d_out, int out_size) {
    const float* x0 = (const float*)d_in[0];
    const int*   i0 = (const int*)d_in[1];
    const float* x1 = (const float*)d_in[2];
    const float* C3 = (const float*)d_in[3];
    const float* C4 = (const float*)d_in[4];
    const int*   p3 = (const int*)d_in[5];
    const int*   p4 = (const int*)d_in[6];
    float* out = (float*)d_out;
    const int E = in_sizes[1];              // i0 has E elements

    prep_kernel<<<1, 32>>>(p3, p4);
    const int blocks = (E + EPB - 1) / EPB;
    tp_kernel<<<blocks, THREADS>>>(x0, i0, x1, C3, C4, out, E);
}

// round 3
// speedup vs baseline: 1.5805x; 1.2946x over previous
#include <cuda_runtime.h>

#define MUL   16
#define DD    4
#define S0    8
#define S1    8
#define SOUT  8
#define NP3   8
#define NP4   4
#define EPB   8          // edges per block-iteration (1 per 16-thread half-warp)
#define THREADS 128
#define GRID_BLOCKS 912  // 152 SMs * 6 resident blocks

// sout-sorted path list + per-path s1 metadata (built by prep_kernel)
__device__ int  d_off[SOUT + 1];
__device__ int2 d_ent[NP3 + NP4];   // .x = s0 slot, .y = W slot (p3: 0..7, p4: 8..11)
__device__ int  d_p3s1[NP3];
__device__ int2 d_p4s[NP4];

__global__ void prep_kernel(const int* __restrict__ p3, const int* __restrict__ p4) {
    if (threadIdx.x == 0 && blockIdx.x == 0) {
        int n = 0;
        for (int so = 0; so < SOUT; ++so) {
            d_off[so] = n;
            for (int p = 0; p < NP3; ++p)
                if (p3[p * 3 + 2] == so) { d_ent[n] = make_int2(p3[p * 3 + 0], p); ++n; }
            for (int p = 0; p < NP4; ++p)
                if (p4[p * 4 + 3] == so) { d_ent[n] = make_int2(p4[p * 4 + 0], NP3 + p); ++n; }
        }
        d_off[SOUT] = n;
        for (int p = 0; p < NP3; ++p) d_p3s1[p] = p3[p * 3 + 1];
        for (int p = 0; p < NP4; ++p) d_p4s[p]  = make_int2(p4[p * 4 + 1], p4[p * 4 + 2]);
    }
}

// uniform-index register select (en.x is uniform across the block -> uniform branch)
__device__ __forceinline__ float4 sel8(const float4 a[8], int s) {
    switch (s) {
        case 0: return a[0]; case 1: return a[1];
        case 2: return a[2]; case 3: return a[3];
        case 4: return a[4]; case 5: return a[5];
        case 6: return a[6]; default: return a[7];
    }
}

__global__ __launch_bounds__(THREADS, 6) void tp_kernel(
    const float* __restrict__ x0, const int* __restrict__ i0,
    const float* __restrict__ x1,
    const float* __restrict__ C3, const float* __restrict__ C4,
    float* __restrict__ out, int E)
{
    __shared__ float sX1[EPB][S1 * DD];         // 1 KB
    __shared__ float sW[EPB][(NP3 + NP4) * 16]; // 6 KB
    __shared__ float sC3[NP3 * DD * 20];        // padded slices
    __shared__ float sC4[NP4 * DD * 68];        // padded slices
    __shared__ int2  sEnt[NP3 + NP4];
    __shared__ int   sOff[SOUT + 1];
    __shared__ int   sP3s1[NP3];
    __shared__ int2  sP4s[NP4];

    const int tid = threadIdx.x;
    const int el  = tid >> 4;     // edge slot (half-warp id), fixed per thread
    const int u   = tid & 15;     // mul index

    // ---- one-time staging: coefficients + metadata ----
    for (int idx = tid; idx < NP3 * DD * DD * DD; idx += THREADS) {
        int slice = idx >> 4;
        sC3[slice * 20 + (idx & 15)] = C3[idx];
    }
    for (int idx = tid; idx < NP4 * DD * DD * DD * DD; idx += THREADS) {
        int slice = idx >> 6;
        sC4[slice * 68 + (idx & 63)] = C4[idx];
    }
    if (tid < NP3 + NP4) sEnt[tid] = d_ent[tid];
    if (tid < SOUT + 1)  sOff[tid] = d_off[tid];
    if (tid < NP3)       sP3s1[tid] = d_p3s1[tid];
    if (tid < NP4)       sP4s[tid]  = d_p4s[tid];
    __syncthreads();   // the ONLY block-wide barrier

    const int ngroups = (E + EPB - 1) / EPB;

    // ---- persistent grid-stride loop; all intra-iteration sync is warp-local ----
    for (int g = blockIdx.x; g < ngroups; g += GRID_BLOCKS) {
        const int e = g * EPB + el;
        const bool valid = (e < E);

        // gather x0 row into registers (8 independent LDG.128)
        float4 a[8];
        if (valid) {
            const long long row = (long long)__ldg(&i0[e]) * (S0 * MUL * DD);
            #pragma unroll
            for (int c = 0; c < 8; ++c)
                a[c] = __ldg((const float4*)&x0[row + c * 64 + u * 4]);
            if (u < 8) {
                float4 v = __ldg((const float4*)&x1[(long long)e * (S1 * DD) + u * 4]);
                *(float4*)&sX1[el][u * 4] = v;
            }
        }
        __syncwarp();

        // W phase: factor out the x1 contractions once per edge (half-warp local)
        if (valid) {
            {   // rank-4 job: (p = u>>2, i = u&3)
                const int p = u >> 2;
                const int s1a = sP4s[p].x, s1b = sP4s[p].y;
                const float* Cs = &sC4[u * 68];
                float4 w = make_float4(0.f, 0.f, 0.f, 0.f);
                #pragma unroll
                for (int j = 0; j < 4; ++j) {
                    const float bj = sX1[el][s1a * 4 + j];
                    #pragma unroll
                    for (int k = 0; k < 4; ++k) {
                        const float bc = bj * sX1[el][s1b * 4 + k];
                        float4 cv = *(const float4*)&Cs[(j * 4 + k) * 4];
                        w.x += bc * cv.x; w.y += bc * cv.y;
                        w.z += bc * cv.z; w.w += bc * cv.w;
                    }
                }
                *(float4*)&sW[el][(NP3 << 4) + u * 4] = w;
            }
            #pragma unroll
            for (int h = 0; h < 2; ++h) {   // rank-3 jobs: u and u+16
                const int job = u + 16 * h;
                const int p = job >> 2;
                const int s1 = sP3s1[p];
                const float* Cs = &sC3[job * 20];
                float4 w = make_float4(0.f, 0.f, 0.f, 0.f);
                #pragma unroll
                for (int j = 0; j < 4; ++j) {
                    const float bj = sX1[el][s1 * 4 + j];
                    float4 cv = *(const float4*)&Cs[j * 4];
                    w.x += bj * cv.x; w.y += bj * cv.y;
                    w.z += bj * cv.z; w.w += bj * cv.w;
                }
                *(float4*)&sW[el][job * 4] = w;
            }
        }
        __syncwarp();

        // contraction + streaming stores
        if (valid) {
            const long long obase = (long long)e * (SOUT * MUL * DD);
            #pragma unroll
            for (int so = 0; so < SOUT; ++so) {
                float4 acc = make_float4(0.f, 0.f, 0.f, 0.f);
                const int end = sOff[so + 1];
                for (int idx = sOff[so]; idx < end; ++idx) {
                    const int2 en = sEnt[idx];
                    const float4 av = sel8(a, en.x);
                    const float4* Wp = (const float4*)&sW[el][en.y * 16];
                    const float4 w0 = Wp[0], w1 = Wp[1], w2 = Wp[2], w3 = Wp[3];
                    acc.x += av.x * w0.x + av.y * w1.x + av.z * w2.x + av.w * w3.x;
                    acc.y += av.x * w0.y + av.y * w1.y + av.z * w2.y + av.w * w3.y;
                    acc.z += av.x * w0.z + av.y * w1.z + av.z * w2.z + av.w * w3.z;
                    acc.w += av.x * w0.w + av.y * w1.w + av.z * w2.w + av.w * w3.w;
                }
                __stwt((float4*)&out[obase + so * 64 + u * 4], acc);
            }
        }
        __syncwarp();   // protect sX1/sW reuse next iteration
    }
}

extern "C" void kernel_launch(void* const* d_in, const int* in_sizes, int n_in,
                              void* d_out, int out_size) {
    const float* x0 = (const float*)d_in[0];
    const int*   i0 = (const int*)d_in[1];
    const float* x1 = (const float*)d_in[2];
    const float* C3 = (const float*)d_in[3];
    const float* C4 = (const float*)d_in[4];
    const int*   p3 = (const int*)d_in[5];
    const int*   p4 = (const int*)d_in[6];
    float* out = (float*)d_out;
    const int E = in_sizes[1];              // i0 has E elements

    prep_kernel<<<1, 32>>>(p3, p4);
    const int ngroups = (E + EPB - 1) / EPB;
    const int blocks = ngroups < GRID_BLOCKS ? ngroups : GRID_BLOCKS;
    tp_kernel<<<blocks, THREADS>>>(x0, i0, x1, C3, C4, out, E);
}